// round 1
// baseline (speedup 1.0000x reference)
#include <cuda_runtime.h>
#include <math.h>

// Problem constants
#define T_   128
#define B_   64
#define TB_  8192      // T*B
#define N_   24        // joints
#define D_   256
#define H_   8
#define F_   32
#define HF_  256       // H*F
#define ND_  6144      // N*D  (input row stride)
#define OUTW_ 6144     // N*H*F (output row stride)
#define M1_  196608    // TB*N rows for KV gemm

// Scratch: q,k,v in [tb][h][n][f] layout, fp32. 3 x 201 MB static device arrays.
__device__ float g_q[TB_ * H_ * N_ * F_];
__device__ float g_k[TB_ * H_ * N_ * F_];
__device__ float g_v[TB_ * H_ * N_ * F_];

// ---------------------------------------------------------------------------
// Kernel 1: K/V projection.
//   C[m][o] = sum_d X[m][d] * W[o][d] + bias[o]
//   X viewed as (TB*N, 256) row-major (contiguous). W is (HF, D) row-major.
//   blockIdx.z = 0 -> K (Wk,bk,g_k), 1 -> V.
//   Output scatter: m=(tb,n), o=(h,f) -> g[(tb*H+h)*N*F + n*F + f]
// ---------------------------------------------------------------------------
#define BM 128
#define BN 128
#define BK 16

__global__ __launch_bounds__(256, 2)
void kv_gemm_kernel(const float* __restrict__ X,
                    const float* __restrict__ Wk, const float* __restrict__ bk,
                    const float* __restrict__ Wv, const float* __restrict__ bv)
{
    const float* W    = (blockIdx.z == 0) ? Wk : Wv;
    const float* bias = (blockIdx.z == 0) ? bk : bv;
    float* dst        = (blockIdx.z == 0) ? g_k : g_v;

    __shared__ float As[BK][BM];
    __shared__ float Bs[BK][BN];

    const int t  = threadIdx.x;        // 0..255
    const int tx = t & 15;
    const int ty = t >> 4;
    const int rowBase = blockIdx.x * BM;
    const int colBase = blockIdx.y * BN;

    const int aRow  = t >> 1;          // 0..127
    const int aCol0 = (t & 1) * 8;     // 0 or 8

    float c[8][8];
#pragma unroll
    for (int i = 0; i < 8; i++)
#pragma unroll
        for (int j = 0; j < 8; j++) c[i][j] = 0.f;

    for (int k0 = 0; k0 < D_; k0 += BK) {
        const float* xp = X + (rowBase + aRow) * D_ + k0 + aCol0;
        const float* wp = W + (colBase + aRow) * D_ + k0 + aCol0;
#pragma unroll
        for (int i = 0; i < 8; i++) As[aCol0 + i][aRow] = xp[i];
#pragma unroll
        for (int i = 0; i < 8; i++) Bs[aCol0 + i][aRow] = wp[i];
        __syncthreads();
#pragma unroll
        for (int kk = 0; kk < BK; kk++) {
            float a[8], b[8];
#pragma unroll
            for (int i = 0; i < 8; i++) a[i] = As[kk][ty * 8 + i];
#pragma unroll
            for (int j = 0; j < 8; j++) b[j] = Bs[kk][tx * 8 + j];
#pragma unroll
            for (int i = 0; i < 8; i++)
#pragma unroll
                for (int j = 0; j < 8; j++) c[i][j] += a[i] * b[j];
        }
        __syncthreads();
    }

#pragma unroll
    for (int i = 0; i < 8; i++) {
        const int m  = rowBase + ty * 8 + i;
        const int tb = m / N_;
        const int n  = m - tb * N_;
#pragma unroll
        for (int j = 0; j < 8; j++) {
            const int o = colBase + tx * 8 + j;
            const int h = o >> 5;
            const int f = o & 31;
            dst[((tb * H_ + h) * N_ + n) * F_ + f] = c[i][j] + bias[o];
        }
    }
}

// ---------------------------------------------------------------------------
// Kernel 2: Q projection for joint n = blockIdx.z.
//   X_n rows: x[tb][n*256 + d]  (row stride ND_)
//   W rows o=(h,f): Wq[((h*N+n)*F + f)*D + d]
// ---------------------------------------------------------------------------
__global__ __launch_bounds__(256, 2)
void q_gemm_kernel(const float* __restrict__ X,
                   const float* __restrict__ Wq, const float* __restrict__ bq)
{
    const int n = blockIdx.z;

    __shared__ float As[BK][BM];
    __shared__ float Bs[BK][BN];

    const int t  = threadIdx.x;
    const int tx = t & 15;
    const int ty = t >> 4;
    const int rowBase = blockIdx.x * BM;   // tb base
    const int colBase = blockIdx.y * BN;   // o base

    const int aRow  = t >> 1;
    const int aCol0 = (t & 1) * 8;

    // weight row pointer for this thread's load row
    const int o_ld = colBase + aRow;
    const int h_ld = o_ld >> 5;
    const int f_ld = o_ld & 31;
    const float* wrow = Wq + (((h_ld * N_ + n) * F_) + f_ld) * D_;

    float c[8][8];
#pragma unroll
    for (int i = 0; i < 8; i++)
#pragma unroll
        for (int j = 0; j < 8; j++) c[i][j] = 0.f;

    for (int k0 = 0; k0 < D_; k0 += BK) {
        const float* xp = X + (rowBase + aRow) * ND_ + n * D_ + k0 + aCol0;
        const float* wp = wrow + k0 + aCol0;
#pragma unroll
        for (int i = 0; i < 8; i++) As[aCol0 + i][aRow] = xp[i];
#pragma unroll
        for (int i = 0; i < 8; i++) Bs[aCol0 + i][aRow] = wp[i];
        __syncthreads();
#pragma unroll
        for (int kk = 0; kk < BK; kk++) {
            float a[8], b[8];
#pragma unroll
            for (int i = 0; i < 8; i++) a[i] = As[kk][ty * 8 + i];
#pragma unroll
            for (int j = 0; j < 8; j++) b[j] = Bs[kk][tx * 8 + j];
#pragma unroll
            for (int i = 0; i < 8; i++)
#pragma unroll
                for (int j = 0; j < 8; j++) c[i][j] += a[i] * b[j];
        }
        __syncthreads();
    }

#pragma unroll
    for (int i = 0; i < 8; i++) {
        const int tb = rowBase + ty * 8 + i;
#pragma unroll
        for (int j = 0; j < 8; j++) {
            const int o = colBase + tx * 8 + j;
            const int h = o >> 5;
            const int f = o & 31;
            g_q[((tb * H_ + h) * N_ + n) * F_ + f] =
                c[i][j] + bq[(h * N_ + n) * F_ + f];
        }
    }
}

// ---------------------------------------------------------------------------
// Kernel 3: attention. 1 warp per (tb, h). grid = (TB, 2), block = 128.
//   scores[n][m] = q[n]·k[m] / sqrt(F); softmax over m (24); out = p @ v.
//   Padded smem (stride 33) to avoid 24-way bank conflicts on k rows.
// ---------------------------------------------------------------------------
__global__ __launch_bounds__(128)
void attn_kernel(float* __restrict__ out)
{
    __shared__ float sq[4][N_][33];
    __shared__ float sk[4][N_][33];
    __shared__ float sv[4][N_][33];
    __shared__ float sp[4][32];

    const int tb   = blockIdx.x;
    const int w    = threadIdx.x >> 5;
    const int lane = threadIdx.x & 31;
    const int h    = blockIdx.y * 4 + w;

    const int base = ((tb * H_ + h) * N_) * F_;
    const float* qb = g_q + base;
    const float* kb = g_k + base;
    const float* vb = g_v + base;

    for (int i = lane; i < N_ * F_; i += 32) {
        const int r = i >> 5, cc = i & 31;
        sq[w][r][cc] = qb[i];
        sk[w][r][cc] = kb[i];
        sv[w][r][cc] = vb[i];
    }
    __syncwarp();

    const float scale = 0.17677669529663687f;  // 1/sqrt(32)

    for (int n = 0; n < N_; n++) {
        float s = -1e30f;
        if (lane < N_) {
            float acc = 0.f;
#pragma unroll
            for (int f = 0; f < F_; f++) acc += sq[w][n][f] * sk[w][lane][f];
            s = acc * scale;
        }
        // max-reduce
        float mx = s;
#pragma unroll
        for (int off = 16; off > 0; off >>= 1)
            mx = fmaxf(mx, __shfl_xor_sync(0xffffffffu, mx, off));
        float p = expf(s - mx);
        if (lane >= N_) p = 0.f;
        float sum = p;
#pragma unroll
        for (int off = 16; off > 0; off >>= 1)
            sum += __shfl_xor_sync(0xffffffffu, sum, off);
        p /= sum;
        sp[w][lane] = p;
        __syncwarp();

        float acc = 0.f;
#pragma unroll
        for (int m = 0; m < N_; m++) acc += sp[w][m] * sv[w][m][lane];
        out[tb * OUTW_ + (n * H_ + h) * F_ + lane] = acc;
        __syncwarp();
    }
}

// ---------------------------------------------------------------------------
extern "C" void kernel_launch(void* const* d_in, const int* in_sizes, int n_in,
                              void* d_out, int out_size)
{
    const float* x  = (const float*)d_in[0];   // (T,B,N*D)
    const float* Wk = (const float*)d_in[1];   // (H,F,D)
    const float* bk = (const float*)d_in[2];   // (H,F)
    const float* Wv = (const float*)d_in[3];
    const float* bv = (const float*)d_in[4];
    const float* Wq = (const float*)d_in[5];   // (H,N,F,D)
    const float* bq = (const float*)d_in[6];   // (H,N,F)
    float* out = (float*)d_out;

    // 1) K and V projections: (196608 x 256) @ (256 x 256)^T, z selects K/V
    dim3 g1(M1_ / BM, HF_ / BN, 2);
    kv_gemm_kernel<<<g1, 256>>>(x, Wk, bk, Wv, bv);

    // 2) Q projection: per joint n, (8192 x 256, lda=6144) @ (256 x 256)^T
    dim3 g2(TB_ / BM, HF_ / BN, N_);
    q_gemm_kernel<<<g2, 256>>>(x, Wq, bq);

    // 3) Attention
    dim3 g3(TB_, 2);
    attn_kernel<<<g3, 128>>>(out);
}

// round 3
// speedup vs baseline: 2.7479x; 2.7479x over previous
#include <cuda_runtime.h>
#include <cstdint>
#include <math.h>

// Problem constants
#define T_    128
#define B_    64
#define TB_   8192      // T*B
#define N_    24        // joints
#define D_    256
#define H_    8
#define F_    32
#define HF_   256       // H*F
#define ND_   6144      // N*D  (input row stride)
#define OUTW_ 6144      // N*H*F
#define M1_   196608    // TB*N rows for KV gemm

// Scratch q,k,v in [tb][h][n][f] layout, fp32.
__device__ float g_q[TB_ * H_ * N_ * F_];
__device__ float g_k[TB_ * H_ * N_ * F_];
__device__ float g_v[TB_ * H_ * N_ * F_];

// ---------------------------------------------------------------------------
// helpers
// ---------------------------------------------------------------------------
__device__ __forceinline__ uint32_t smem_u32(const void* p) {
    uint32_t a;
    asm("{ .reg .u64 t; cvta.to.shared.u64 t, %1; cvt.u32.u64 %0, t; }"
        : "=r"(a) : "l"(p));
    return a;
}
__device__ __forceinline__ void cp_async16(uint32_t dst, const void* src) {
    asm volatile("cp.async.cg.shared.global [%0], [%1], 16;"
                 :: "r"(dst), "l"(src) : "memory");
}
__device__ __forceinline__ void cp_commit() {
    asm volatile("cp.async.commit_group;" ::: "memory");
}
__device__ __forceinline__ void cp_wait1() {
    asm volatile("cp.async.wait_group 1;" ::: "memory");
}
__device__ __forceinline__ void cp_wait0() {
    asm volatile("cp.async.wait_group 0;" ::: "memory");
}
// fp32 (smem) -> tf32 reg with round-to-nearest
__device__ __forceinline__ uint32_t ld_tf32(const float* p) {
    uint32_t u;
    asm("cvt.rna.tf32.f32 %0, %1;" : "=r"(u) : "f"(*p));
    return u;
}
__device__ __forceinline__ void mma_tf32(float c[4], const uint32_t a[4],
                                         const uint32_t b[2]) {
    asm volatile(
        "mma.sync.aligned.m16n8k8.row.col.f32.tf32.tf32.f32 "
        "{%0,%1,%2,%3}, {%4,%5,%6,%7}, {%8,%9}, {%0,%1,%2,%3};"
        : "+f"(c[0]), "+f"(c[1]), "+f"(c[2]), "+f"(c[3])
        : "r"(a[0]), "r"(a[1]), "r"(a[2]), "r"(a[3]), "r"(b[0]), "r"(b[1]));
}

// Smem geometry: rows padded to 36 floats (conflict-free frags, 16B aligned)
#define APAD   36
#define A_BYTES (128 * APAD * 4)        // 18432
#define B_BYTES (256 * APAD * 4)        // 36864
#define STAGE   (A_BYTES + B_BYTES)     // 55296
#define GSMEM_BYTES (2 * STAGE + 1024)  // + bias

// ---------------------------------------------------------------------------
// Shared GEMM core: computes C(128x256) = A(128x256) * B(256x256)^T + bias
// per-CTA, warp tile 64x64, mma m16n8k8 tf32, 2-stage cp.async pipeline.
// Loader lambdas differ between KV and Q, so it's duplicated in each kernel.
// ---------------------------------------------------------------------------
#define GEMM_COMPUTE_CHUNK(sA, sB)                                          \
    {                                                                       \
        _Pragma("unroll")                                                   \
        for (int ks = 0; ks < 4; ks++) {                                    \
            const int kk = ks * 8;                                          \
            uint32_t af[4][4];                                              \
            _Pragma("unroll")                                               \
            for (int mi = 0; mi < 4; mi++) {                                \
                const int r = mWarp + mi * 16 + gid;                        \
                af[mi][0] = ld_tf32(sA + (r)     * APAD + kk + tig);        \
                af[mi][1] = ld_tf32(sA + (r + 8) * APAD + kk + tig);        \
                af[mi][2] = ld_tf32(sA + (r)     * APAD + kk + tig + 4);    \
                af[mi][3] = ld_tf32(sA + (r + 8) * APAD + kk + tig + 4);    \
            }                                                               \
            uint32_t bf[8][2];                                              \
            _Pragma("unroll")                                               \
            for (int ni = 0; ni < 8; ni++) {                                \
                const int nn = nWarp + ni * 8 + gid;                        \
                bf[ni][0] = ld_tf32(sB + nn * APAD + kk + tig);             \
                bf[ni][1] = ld_tf32(sB + nn * APAD + kk + tig + 4);         \
            }                                                               \
            _Pragma("unroll")                                               \
            for (int mi = 0; mi < 4; mi++)                                  \
                _Pragma("unroll")                                           \
                for (int ni = 0; ni < 8; ni++)                              \
                    mma_tf32(c[mi][ni], af[mi], bf[ni]);                    \
        }                                                                   \
    }

// ---------------------------------------------------------------------------
// Kernel 1: K or V projection (blockIdx.z selects).
//   X viewed (196608, 256) row-major; W (256,256) row-major (o = h*32+f).
// ---------------------------------------------------------------------------
__global__ void __launch_bounds__(256, 1)
kv_mma_kernel(const float* __restrict__ X,
              const float* __restrict__ Wk, const float* __restrict__ bk,
              const float* __restrict__ Wv, const float* __restrict__ bv)
{
    extern __shared__ char smem[];
    const float* W    = (blockIdx.z == 0) ? Wk : Wv;
    const float* bias = (blockIdx.z == 0) ? bk : bv;
    float* dst        = (blockIdx.z == 0) ? g_k : g_v;

    const int tid  = threadIdx.x;
    const int w    = tid >> 5, lane = tid & 31;
    const int gid  = lane >> 2, tig = lane & 3;
    const int mWarp = (w & 1) * 64;
    const int nWarp = (w >> 1) * 64;
    const int rowBase = blockIdx.x * 128;
    const uint32_t sb = smem_u32(smem);

    float* sbias = (float*)(smem + 2 * STAGE);
    sbias[tid] = bias[tid];

    float c[4][8][4];
#pragma unroll
    for (int mi = 0; mi < 4; mi++)
#pragma unroll
        for (int ni = 0; ni < 8; ni++)
#pragma unroll
            for (int j = 0; j < 4; j++) c[mi][ni][j] = 0.f;

    // stage loader
    auto load_stage = [&](int ch) {
        const int s = ch & 1;
        const int k0 = ch * 32;
        const uint32_t aBase = sb + s * STAGE;
        const uint32_t bBase = aBase + A_BYTES;
#pragma unroll
        for (int j = 0; j < 4; j++) {           // A: 128 x 32
            const int e = tid + 256 * j;
            const int r = e >> 3, c4 = e & 7;
            cp_async16(aBase + (uint32_t)(r * APAD + c4 * 4) * 4,
                       X + (size_t)(rowBase + r) * D_ + k0 + c4 * 4);
        }
#pragma unroll
        for (int j = 0; j < 8; j++) {           // B: 256 x 32
            const int e = tid + 256 * j;
            const int o = e >> 3, c4 = e & 7;
            cp_async16(bBase + (uint32_t)(o * APAD + c4 * 4) * 4,
                       W + (size_t)o * D_ + k0 + c4 * 4);
        }
    };

    load_stage(0); cp_commit();
    load_stage(1); cp_commit();

    for (int ch = 0; ch < 8; ch++) {
        if (ch < 7) cp_wait1(); else cp_wait0();
        __syncthreads();
        const float* sA = (const float*)(smem + (ch & 1) * STAGE);
        const float* sB = (const float*)(smem + (ch & 1) * STAGE + A_BYTES);
        GEMM_COMPUTE_CHUNK(sA, sB);
        __syncthreads();
        if (ch + 2 < 8) { load_stage(ch + 2); cp_commit(); }
    }

    // epilogue: bias + scatter to [tb][h][n][f]
#pragma unroll
    for (int mi = 0; mi < 4; mi++) {
        const int r0 = rowBase + mWarp + mi * 16 + gid;
#pragma unroll
        for (int rr = 0; rr < 2; rr++) {
            const int m = r0 + rr * 8;
            const int tb = m / N_, n = m - tb * N_;
#pragma unroll
            for (int ni = 0; ni < 8; ni++) {
                const int o = nWarp + ni * 8 + tig * 2;
                const int h = o >> 5, f = o & 31;
                float2 v;
                v.x = c[mi][ni][2 * rr + 0] + sbias[o];
                v.y = c[mi][ni][2 * rr + 1] + sbias[o + 1];
                *(float2*)&dst[(((size_t)tb * H_ + h) * N_ + n) * F_ + f] = v;
            }
        }
    }
}

// ---------------------------------------------------------------------------
// Kernel 2: Q projection for joint n = blockIdx.z.
// ---------------------------------------------------------------------------
__global__ void __launch_bounds__(256, 1)
q_mma_kernel(const float* __restrict__ X,
             const float* __restrict__ Wq, const float* __restrict__ bq)
{
    extern __shared__ char smem[];
    const int nJ = blockIdx.z;

    const int tid  = threadIdx.x;
    const int w    = tid >> 5, lane = tid & 31;
    const int gid  = lane >> 2, tig = lane & 3;
    const int mWarp = (w & 1) * 64;
    const int nWarp = (w >> 1) * 64;
    const int rowBase = blockIdx.x * 128;
    const uint32_t sb = smem_u32(smem);

    float* sbias = (float*)(smem + 2 * STAGE);
    {
        const int h = tid >> 5, f = tid & 31;
        sbias[tid] = bq[(h * N_ + nJ) * F_ + f];
    }

    float c[4][8][4];
#pragma unroll
    for (int mi = 0; mi < 4; mi++)
#pragma unroll
        for (int ni = 0; ni < 8; ni++)
#pragma unroll
            for (int j = 0; j < 4; j++) c[mi][ni][j] = 0.f;

    auto load_stage = [&](int ch) {
        const int s = ch & 1;
        const int k0 = ch * 32;
        const uint32_t aBase = sb + s * STAGE;
        const uint32_t bBase = aBase + A_BYTES;
#pragma unroll
        for (int j = 0; j < 4; j++) {           // A: rows tb, stride ND_
            const int e = tid + 256 * j;
            const int r = e >> 3, c4 = e & 7;
            cp_async16(aBase + (uint32_t)(r * APAD + c4 * 4) * 4,
                       X + (size_t)(rowBase + r) * ND_ + nJ * D_ + k0 + c4 * 4);
        }
#pragma unroll
        for (int j = 0; j < 8; j++) {           // B: Wq[h][nJ][f][:]
            const int e = tid + 256 * j;
            const int o = e >> 3, c4 = e & 7;
            const int h = o >> 5, f = o & 31;
            cp_async16(bBase + (uint32_t)(o * APAD + c4 * 4) * 4,
                       Wq + ((size_t)(h * N_ + nJ) * F_ + f) * D_ + k0 + c4 * 4);
        }
    };

    load_stage(0); cp_commit();
    load_stage(1); cp_commit();

    for (int ch = 0; ch < 8; ch++) {
        if (ch < 7) cp_wait1(); else cp_wait0();
        __syncthreads();
        const float* sA = (const float*)(smem + (ch & 1) * STAGE);
        const float* sB = (const float*)(smem + (ch & 1) * STAGE + A_BYTES);
        GEMM_COMPUTE_CHUNK(sA, sB);
        __syncthreads();
        if (ch + 2 < 8) { load_stage(ch + 2); cp_commit(); }
    }

#pragma unroll
    for (int mi = 0; mi < 4; mi++) {
        const int r0 = rowBase + mWarp + mi * 16 + gid;
#pragma unroll
        for (int rr = 0; rr < 2; rr++) {
            const int tb = r0 + rr * 8;
#pragma unroll
            for (int ni = 0; ni < 8; ni++) {
                const int o = nWarp + ni * 8 + tig * 2;
                const int h = o >> 5, f = o & 31;
                float2 v;
                v.x = c[mi][ni][2 * rr + 0] + sbias[o];
                v.y = c[mi][ni][2 * rr + 1] + sbias[o + 1];
                *(float2*)&g_q[(((size_t)tb * H_ + h) * N_ + nJ) * F_ + f] = v;
            }
        }
    }
}

// ---------------------------------------------------------------------------
// Kernel 3: attention. 1 warp per (tb, h).
// ---------------------------------------------------------------------------
__global__ __launch_bounds__(128)
void attn_kernel(float* __restrict__ out)
{
    __shared__ float sq[4][N_][33];
    __shared__ float sk[4][N_][33];
    __shared__ float sv[4][N_][33];
    __shared__ float sp[4][32];

    const int tb   = blockIdx.x;
    const int w    = threadIdx.x >> 5;
    const int lane = threadIdx.x & 31;
    const int h    = blockIdx.y * 4 + w;

    const int base = ((tb * H_ + h) * N_) * F_;
    const float* qb = g_q + base;
    const float* kb = g_k + base;
    const float* vb = g_v + base;

    for (int i = lane; i < N_ * F_; i += 32) {
        const int r = i >> 5, cc = i & 31;
        sq[w][r][cc] = qb[i];
        sk[w][r][cc] = kb[i];
        sv[w][r][cc] = vb[i];
    }
    __syncwarp();

    const float scale = 0.17677669529663687f;  // 1/sqrt(32)

    for (int n = 0; n < N_; n++) {
        float s = -1e30f;
        if (lane < N_) {
            float acc = 0.f;
#pragma unroll
            for (int f = 0; f < F_; f++) acc += sq[w][n][f] * sk[w][lane][f];
            s = acc * scale;
        }
        float mx = s;
#pragma unroll
        for (int off = 16; off > 0; off >>= 1)
            mx = fmaxf(mx, __shfl_xor_sync(0xffffffffu, mx, off));
        float p = expf(s - mx);
        if (lane >= N_) p = 0.f;
        float sum = p;
#pragma unroll
        for (int off = 16; off > 0; off >>= 1)
            sum += __shfl_xor_sync(0xffffffffu, sum, off);
        p /= sum;
        sp[w][lane] = p;
        __syncwarp();

        float acc = 0.f;
#pragma unroll
        for (int m = 0; m < N_; m++) acc += sp[w][m] * sv[w][m][lane];
        out[tb * OUTW_ + (n * H_ + h) * F_ + lane] = acc;
        __syncwarp();
    }
}

// ---------------------------------------------------------------------------
extern "C" void kernel_launch(void* const* d_in, const int* in_sizes, int n_in,
                              void* d_out, int out_size)
{
    const float* x  = (const float*)d_in[0];
    const float* Wk = (const float*)d_in[1];
    const float* bk = (const float*)d_in[2];
    const float* Wv = (const float*)d_in[3];
    const float* bv = (const float*)d_in[4];
    const float* Wq = (const float*)d_in[5];
    const float* bq = (const float*)d_in[6];
    float* out = (float*)d_out;

    static int attr_done = 0;
    if (!attr_done) {
        cudaFuncSetAttribute(kv_mma_kernel,
                             cudaFuncAttributeMaxDynamicSharedMemorySize, GSMEM_BYTES);
        cudaFuncSetAttribute(q_mma_kernel,
                             cudaFuncAttributeMaxDynamicSharedMemorySize, GSMEM_BYTES);
        attr_done = 1;
    }

    dim3 g1(M1_ / 128, 1, 2);
    kv_mma_kernel<<<g1, 256, GSMEM_BYTES>>>(x, Wk, bk, Wv, bv);

    dim3 g2(TB_ / 128, 1, N_);
    q_mma_kernel<<<g2, 256, GSMEM_BYTES>>>(x, Wq, bq);

    dim3 g3(TB_, 2);
    attn_kernel<<<g3, 128>>>(out);
}